// round 5
// baseline (speedup 1.0000x reference)
#include <cuda_runtime.h>
#include <cuda_fp16.h>
#include <cstdint>

// ---------------- problem constants ----------------
#define VOCAB 32000
#define EMB   64
#define BATCH 4
#define SEQ   2048
#define MROWS (BATCH * SEQ)   // 8192

// GEMM tiling
#define BM 128
#define BN 256
#define HPITCH 72                        // halves; conflict-free fragment LDS

// device scratch
__device__ __half g_A[MROWS * EMB];       // prefix means, fp16
__device__ __half g_Wh[VOCAB * EMB];      // W, fp16
__device__ float  g_S[MROWS * EMB];       // fp32 chunk-local prefix sums
__device__ float  g_csum[BATCH * 32 * EMB];
__device__ float  g_coff[BATCH * 32 * EMB];

// ---------------- helpers ----------------
__device__ __forceinline__ uint32_t smem_u32(const void* p) {
    uint32_t a;
    asm("{ .reg .u64 t; cvta.to.shared.u64 t, %1; cvt.u32.u64 %0, t; }" : "=r"(a) : "l"(p));
    return a;
}
__device__ __forceinline__ void mma_f16(float c[4],
                                        uint32_t a0, uint32_t a1, uint32_t a2, uint32_t a3,
                                        uint32_t b0, uint32_t b1) {
    asm volatile(
        "mma.sync.aligned.m16n8k16.row.col.f32.f16.f16.f32 "
        "{%0,%1,%2,%3}, {%4,%5,%6,%7}, {%8,%9}, {%0,%1,%2,%3};"
        : "+f"(c[0]), "+f"(c[1]), "+f"(c[2]), "+f"(c[3])
        : "r"(a0), "r"(a1), "r"(a2), "r"(a3), "r"(b0), "r"(b1));
}
#define CP_ASYNC16(saddr, gptr) \
    asm volatile("cp.async.cg.shared.global [%0], [%1], 16;" :: "r"(saddr), "l"(gptr))
#define CP_COMMIT() asm volatile("cp.async.commit_group;" ::: "memory")
#define CP_WAIT(n)  asm volatile("cp.async.wait_group %0;" :: "n"(n) : "memory")

// ---------------- kernel 0: W -> fp16 copy ----------------
__global__ void __launch_bounds__(256) wprep_kernel(const float* __restrict__ W) {
    const int i = blockIdx.x * 256 + threadIdx.x;  // 8 floats per thread
    const float4* src = reinterpret_cast<const float4*>(W) + i * 2;
    float4 v0 = src[0];
    float4 v1 = src[1];
    __half2 h[4];
    h[0] = __floats2half2_rn(v0.x, v0.y);
    h[1] = __floats2half2_rn(v0.z, v0.w);
    h[2] = __floats2half2_rn(v1.x, v1.y);
    h[3] = __floats2half2_rn(v1.z, v1.w);
    *reinterpret_cast<uint4*>(g_Wh + (size_t)i * 8) = *reinterpret_cast<uint4*>(h);
}

// ---------------- prefix phase 1: chunk-local gather + scan (unscaled fp32) ----------------
__global__ void __launch_bounds__(512) p1_kernel(const float* __restrict__ emb,
                                                 const int* __restrict__ x) {
    __shared__ float ebuf[64 * 64];
    const int c = blockIdx.x, b = blockIdx.y;
    const int t = threadIdx.x;
    const int i = t >> 3, q = t & 7;
    const int p0 = c * 64;
    const int idx = x[b * SEQ + p0 + i];
    const float4* src = reinterpret_cast<const float4*>(emb + (size_t)idx * EMB) + q * 2;
    float4 v0 = src[0];
    float4 v1 = src[1];
    *reinterpret_cast<float4*>(ebuf + i * 64 + q * 8)     = v0;
    *reinterpret_cast<float4*>(ebuf + i * 64 + q * 8 + 4) = v1;
    __syncthreads();
    if (t < 64) {
        float run = 0.0f;
        #pragma unroll 8
        for (int p = 0; p < 64; ++p) {
            run += ebuf[p * 64 + t];
            g_S[(size_t)(b * SEQ + p0 + p) * EMB + t] = run;
        }
        g_csum[(b * 32 + c) * EMB + t] = run;
    }
}

// ---------------- prefix phase 2: per-batch exclusive scan of chunk sums ----------------
__global__ void __launch_bounds__(64) p2_kernel() {
    const int b = blockIdx.x, e = threadIdx.x;
    float off = 0.0f;
    #pragma unroll
    for (int c = 0; c < 32; ++c) {
        g_coff[(b * 32 + c) * EMB + e] = off;
        off += g_csum[(b * 32 + c) * EMB + e];
    }
}

// ---------------- prefix phase 3: apply offsets, scale, fp16-round ----------------
__global__ void __launch_bounds__(512) p3_kernel() {
    const int c = blockIdx.x, b = blockIdx.y;
    const int t = threadIdx.x;
    const int i = t >> 3, q = t & 7;
    const int p = c * 64 + i;
    const float inv = __fdividef(1.0f, (float)(p + 1));
    const float* base  = g_S + (size_t)(b * SEQ + p) * EMB + q * 8;
    const float* obase = g_coff + (size_t)(b * 32 + c) * EMB + q * 8;
    float4 a0 = *reinterpret_cast<const float4*>(base);
    float4 a1 = *reinterpret_cast<const float4*>(base + 4);
    float4 o0 = *reinterpret_cast<const float4*>(obase);
    float4 o1 = *reinterpret_cast<const float4*>(obase + 4);
    __half2 h[4];
    h[0] = __floats2half2_rn((a0.x + o0.x) * inv, (a0.y + o0.y) * inv);
    h[1] = __floats2half2_rn((a0.z + o0.z) * inv, (a0.w + o0.w) * inv);
    h[2] = __floats2half2_rn((a1.x + o1.x) * inv, (a1.y + o1.y) * inv);
    h[3] = __floats2half2_rn((a1.z + o1.z) * inv, (a1.w + o1.w) * inv);
    *reinterpret_cast<uint4*>(g_A + (size_t)(b * SEQ + p) * EMB + q * 8) =
        *reinterpret_cast<uint4*>(h);
}

// ---------------- GEMM: fp16 mma.sync, BN=256, A via direct LDG, barrier-free j-loop ----
// out[m, n] = sum_k A[m,k] * W[n,k] + bias[n]
__global__ void __launch_bounds__(512, 1) gemm_kernel(const float* __restrict__ bias,
                                                      float* __restrict__ out) {
    __shared__ __half Bs[BN * HPITCH];    // 36864 B

    const int tid  = threadIdx.x;
    const int wid  = tid >> 5;            // 0..15
    const int lane = tid & 31;
    const int gid  = lane >> 2;           // 0..7
    const int tig  = lane & 3;            // 0..3
    const int mw   = wid >> 3;            // warp M index 0..1 (64 rows each)
    const int nw   = wid & 7;             // warp N index 0..7 (32 cols each)
    const int n0   = blockIdx.x * BN;
    const int yb   = blockIdx.y;          // 0..7

    const uint32_t sB = smem_u32(Bs);

    // ---- stage B tile [256 x 64] once (2048 x 16B, 4 per thread) ----
    {
        const __half* gB = g_Wh + (size_t)n0 * EMB;
        #pragma unroll
        for (int it = 0; it < 4; ++it) {
            const int lin = it * 512 + tid;
            const int r = lin >> 3, f8 = lin & 7;
            CP_ASYNC16(sB + (uint32_t)(r * HPITCH + f8 * 8) * 2, gB + r * EMB + f8 * 8);
        }
        CP_COMMIT();
    }

    // bias -> registers
    float bias_r[4][2];
    #pragma unroll
    for (int nt = 0; nt < 4; ++nt) {
        float2 bv = *reinterpret_cast<const float2*>(bias + n0 + nw * 32 + nt * 8 + 2 * tig);
        bias_r[nt][0] = bv.x;
        bias_r[nt][1] = bv.y;
    }

    CP_WAIT(0);
    __syncthreads();   // only barrier in the kernel; B is read-only afterwards

    #pragma unroll 1
    for (int j = 0; j < 8; ++j) {
        const int m0 = (yb + j * 8) * BM;
        // warp's A base: rows [m0 + mw*64, +64), row-major 64 halves
        const __half* __restrict__ Ag = g_A + (size_t)(m0 + mw * 64) * EMB;

        float acc[4][4][4];
        #pragma unroll
        for (int mt = 0; mt < 4; ++mt)
            #pragma unroll
            for (int nt = 0; nt < 4; ++nt)
                #pragma unroll
                for (int rr = 0; rr < 4; ++rr) acc[mt][nt][rr] = 0.0f;

        #pragma unroll
        for (int ks = 0; ks < 4; ++ks) {
            const int k0 = ks * 16;
            uint32_t a[4][4];
            #pragma unroll
            for (int mt = 0; mt < 4; ++mt) {
                const __half* ap = Ag + (mt * 16 + gid) * EMB + k0 + 2 * tig;
                a[mt][0] = *reinterpret_cast<const uint32_t*>(ap);
                a[mt][1] = *reinterpret_cast<const uint32_t*>(ap + 8 * EMB);
                a[mt][2] = *reinterpret_cast<const uint32_t*>(ap + 8);
                a[mt][3] = *reinterpret_cast<const uint32_t*>(ap + 8 * EMB + 8);
            }
            uint32_t bb[4][2];
            #pragma unroll
            for (int nt = 0; nt < 4; ++nt) {
                const __half* bp = Bs + (nw * 32 + nt * 8 + gid) * HPITCH + k0 + 2 * tig;
                bb[nt][0] = *reinterpret_cast<const uint32_t*>(bp);
                bb[nt][1] = *reinterpret_cast<const uint32_t*>(bp + 8);
            }
            #pragma unroll
            for (int mt = 0; mt < 4; ++mt)
                #pragma unroll
                for (int nt = 0; nt < 4; ++nt)
                    mma_f16(acc[mt][nt], a[mt][0], a[mt][1], a[mt][2], a[mt][3],
                            bb[nt][0], bb[nt][1]);
        }

        // ---- epilogue: direct STG.64 from fragments + bias (no barrier) ----
        #pragma unroll
        for (int mt = 0; mt < 4; ++mt) {
            const int row0 = m0 + mw * 64 + mt * 16 + gid;
            float* orow0 = out + (size_t)row0 * VOCAB + n0;
            #pragma unroll
            for (int nt = 0; nt < 4; ++nt) {
                const int col = nw * 32 + nt * 8 + 2 * tig;
                float2 v0 = make_float2(acc[mt][nt][0] + bias_r[nt][0],
                                        acc[mt][nt][1] + bias_r[nt][1]);
                float2 v1 = make_float2(acc[mt][nt][2] + bias_r[nt][0],
                                        acc[mt][nt][3] + bias_r[nt][1]);
                *reinterpret_cast<float2*>(orow0 + col) = v0;
                *reinterpret_cast<float2*>(orow0 + (size_t)8 * VOCAB + col) = v1;
            }
        }
    }
}

// ---------------- launch ----------------
extern "C" void kernel_launch(void* const* d_in, const int* in_sizes, int n_in,
                              void* d_out, int out_size) {
    const float* emb  = (const float*)d_in[0];   // [32000, 64] f32
    const float* Wm   = (const float*)d_in[1];   // [32000, 64] f32
    const float* bias = (const float*)d_in[2];   // [32000] f32
    const int*   x    = (const int*)d_in[3];     // [4, 2048] i32
    float* out = (float*)d_out;                  // [4, 2048, 32000] f32

    wprep_kernel<<<(VOCAB * EMB / 8) / 256, 256>>>(Wm);   // 1000 blocks
    p1_kernel<<<dim3(32, BATCH), 512>>>(emb, x);
    p2_kernel<<<BATCH, 64>>>();
    p3_kernel<<<dim3(32, BATCH), 512>>>();

    dim3 grid(VOCAB / BN, 8);   // (125, 8)
    gemm_kernel<<<grid, 512>>>(bias, out);
}

// round 6
// speedup vs baseline: 1.8470x; 1.8470x over previous
#include <cuda_runtime.h>
#include <cuda_fp16.h>
#include <cstdint>

// ---------------- problem constants ----------------
#define VOCAB 32000
#define EMB   64
#define BATCH 4
#define SEQ   2048
#define MROWS (BATCH * SEQ)   // 8192

// GEMM tiling
#define BM 128
#define BN 128
#define HPITCH 72                        // halves; conflict-free fragment LDS
#define TILE_BYTES (128 * HPITCH * 2)    // 18432

// smem: B tile + double-buffered A tiles + epilogue staging
#define SOFF_B   0
#define SOFF_A0  TILE_BYTES
#define SOFF_A1  (2 * TILE_BYTES)
#define SOFF_STG (3 * TILE_BYTES)        // 8 warps x 16x36 fp32 = 18432
#define SMEM_SZ  (4 * TILE_BYTES)        // 73728 -> 2 CTAs/SM

// device scratch
__device__ __half g_A[MROWS * EMB];       // prefix means, fp16
__device__ __half g_Wh[VOCAB * EMB];      // W, fp16
__device__ float  g_S[MROWS * EMB];       // fp32 chunk-local prefix sums
__device__ float  g_csum[BATCH * 32 * EMB];
__device__ float  g_coff[BATCH * 32 * EMB];

// ---------------- helpers ----------------
__device__ __forceinline__ uint32_t smem_u32(const void* p) {
    uint32_t a;
    asm("{ .reg .u64 t; cvta.to.shared.u64 t, %1; cvt.u32.u64 %0, t; }" : "=r"(a) : "l"(p));
    return a;
}
__device__ __forceinline__ void mma_f16(float c[4],
                                        uint32_t a0, uint32_t a1, uint32_t a2, uint32_t a3,
                                        uint32_t b0, uint32_t b1) {
    asm volatile(
        "mma.sync.aligned.m16n8k16.row.col.f32.f16.f16.f32 "
        "{%0,%1,%2,%3}, {%4,%5,%6,%7}, {%8,%9}, {%0,%1,%2,%3};"
        : "+f"(c[0]), "+f"(c[1]), "+f"(c[2]), "+f"(c[3])
        : "r"(a0), "r"(a1), "r"(a2), "r"(a3), "r"(b0), "r"(b1));
}
#define CP_ASYNC16(saddr, gptr) \
    asm volatile("cp.async.cg.shared.global [%0], [%1], 16;" :: "r"(saddr), "l"(gptr))
#define CP_COMMIT() asm volatile("cp.async.commit_group;" ::: "memory")
#define CP_WAIT(n)  asm volatile("cp.async.wait_group %0;" :: "n"(n) : "memory")

// ---------------- kernel 0: W -> fp16 copy ----------------
__global__ void __launch_bounds__(256) wprep_kernel(const float* __restrict__ W) {
    const int i = blockIdx.x * 256 + threadIdx.x;  // 8 floats per thread
    const float4* src = reinterpret_cast<const float4*>(W) + i * 2;
    float4 v0 = src[0];
    float4 v1 = src[1];
    __half2 h[4];
    h[0] = __floats2half2_rn(v0.x, v0.y);
    h[1] = __floats2half2_rn(v0.z, v0.w);
    h[2] = __floats2half2_rn(v1.x, v1.y);
    h[3] = __floats2half2_rn(v1.z, v1.w);
    *reinterpret_cast<uint4*>(g_Wh + (size_t)i * 8) = *reinterpret_cast<uint4*>(h);
}

// ---------------- prefix phase 1: chunk-local gather + scan (unscaled fp32) ----------------
__global__ void __launch_bounds__(512) p1_kernel(const float* __restrict__ emb,
                                                 const int* __restrict__ x) {
    __shared__ float ebuf[64 * 64];
    const int c = blockIdx.x, b = blockIdx.y;
    const int t = threadIdx.x;
    const int i = t >> 3, q = t & 7;
    const int p0 = c * 64;
    const int idx = x[b * SEQ + p0 + i];
    const float4* src = reinterpret_cast<const float4*>(emb + (size_t)idx * EMB) + q * 2;
    float4 v0 = src[0];
    float4 v1 = src[1];
    *reinterpret_cast<float4*>(ebuf + i * 64 + q * 8)     = v0;
    *reinterpret_cast<float4*>(ebuf + i * 64 + q * 8 + 4) = v1;
    __syncthreads();
    if (t < 64) {
        float run = 0.0f;
        #pragma unroll 8
        for (int p = 0; p < 64; ++p) {
            run += ebuf[p * 64 + t];
            g_S[(size_t)(b * SEQ + p0 + p) * EMB + t] = run;
        }
        g_csum[(b * 32 + c) * EMB + t] = run;
    }
}

// ---------------- prefix phase 2: per-batch exclusive scan of chunk sums ----------------
__global__ void __launch_bounds__(64) p2_kernel() {
    const int b = blockIdx.x, e = threadIdx.x;
    float off = 0.0f;
    #pragma unroll
    for (int c = 0; c < 32; ++c) {
        g_coff[(b * 32 + c) * EMB + e] = off;
        off += g_csum[(b * 32 + c) * EMB + e];
    }
}

// ---------------- prefix phase 3: apply offsets, scale, fp16-round ----------------
__global__ void __launch_bounds__(512) p3_kernel() {
    const int c = blockIdx.x, b = blockIdx.y;
    const int t = threadIdx.x;
    const int i = t >> 3, q = t & 7;
    const int p = c * 64 + i;
    const float inv = __fdividef(1.0f, (float)(p + 1));
    const float* base  = g_S + (size_t)(b * SEQ + p) * EMB + q * 8;
    const float* obase = g_coff + (size_t)(b * 32 + c) * EMB + q * 8;
    float4 a0 = *reinterpret_cast<const float4*>(base);
    float4 a1 = *reinterpret_cast<const float4*>(base + 4);
    float4 o0 = *reinterpret_cast<const float4*>(obase);
    float4 o1 = *reinterpret_cast<const float4*>(obase + 4);
    __half2 h[4];
    h[0] = __floats2half2_rn((a0.x + o0.x) * inv, (a0.y + o0.y) * inv);
    h[1] = __floats2half2_rn((a0.z + o0.z) * inv, (a0.w + o0.w) * inv);
    h[2] = __floats2half2_rn((a1.x + o1.x) * inv, (a1.y + o1.y) * inv);
    h[3] = __floats2half2_rn((a1.z + o1.z) * inv, (a1.w + o1.w) * inv);
    *reinterpret_cast<uint4*>(g_A + (size_t)(b * SEQ + p) * EMB + q * 8) =
        *reinterpret_cast<uint4*>(h);
}

// ---------------- GEMM: fp16 mma.sync, double-buffered A, coalesced staged epilogue ----
// out[m, n] = sum_k A[m,k] * W[n,k] + bias[n]
__global__ void __launch_bounds__(256, 2) gemm_kernel(const float* __restrict__ bias,
                                                      float* __restrict__ out) {
    extern __shared__ char smem[];
    __half* Bs    = reinterpret_cast<__half*>(smem + SOFF_B);
    __half* Abuf0 = reinterpret_cast<__half*>(smem + SOFF_A0);
    __half* Abuf1 = reinterpret_cast<__half*>(smem + SOFF_A1);

    const int tid  = threadIdx.x;
    const int wid  = tid >> 5;
    const int lane = tid & 31;
    const int gid  = lane >> 2;   // 0..7
    const int tig  = lane & 3;    // 0..3
    const int mw   = wid >> 2;    // warp M index 0..1
    const int nw   = wid & 3;     // warp N index 0..3
    const int n0   = blockIdx.x * BN;
    const int yb   = blockIdx.y;  // 0..7

    const uint32_t sB  = smem_u32(Bs);
    const uint32_t sA0 = smem_u32(Abuf0);
    const uint32_t sA1 = smem_u32(Abuf1);

    // per-warp epilogue staging: 16 rows x pitch 36 fp32
    float* stg = reinterpret_cast<float*>(smem + SOFF_STG) + wid * (16 * 36);
    const int sr = lane >> 3;   // 0..3  row-in-group for STG
    const int sc = lane & 7;    // 0..7  float4 column chunk

    // bias -> registers
    float bias_r[4][2];
    #pragma unroll
    for (int nt = 0; nt < 4; ++nt) {
        float2 bv = *reinterpret_cast<const float2*>(bias + n0 + nw * 32 + nt * 8 + 2 * tig);
        bias_r[nt][0] = bv.x;
        bias_r[nt][1] = bv.y;
    }

    // issue B tile + A tile j=0
    {
        const __half* gB = g_Wh + (size_t)n0 * EMB;
        #pragma unroll
        for (int it = 0; it < 4; ++it) {
            const int lin = it * 256 + tid;
            const int r = lin >> 3, f8 = lin & 7;      // f8: 16B chunk
            CP_ASYNC16(sB + (uint32_t)(r * HPITCH + f8 * 8) * 2, gB + r * EMB + f8 * 8);
        }
        const __half* gA = g_A + (size_t)(yb * BM) * EMB;
        #pragma unroll
        for (int it = 0; it < 4; ++it) {
            const int lin = it * 256 + tid;
            const int r = lin >> 3, f8 = lin & 7;
            CP_ASYNC16(sA0 + (uint32_t)(r * HPITCH + f8 * 8) * 2, gA + r * EMB + f8 * 8);
        }
        CP_COMMIT();
    }

    #pragma unroll 1
    for (int j = 0; j < 8; ++j) {
        if (j < 7) {
            const uint32_t sdst = (j & 1) ? sA0 : sA1;
            const __half* gA = g_A + (size_t)((yb + (j + 1) * 8) * BM) * EMB;
            #pragma unroll
            for (int it = 0; it < 4; ++it) {
                const int lin = it * 256 + tid;
                const int r = lin >> 3, f8 = lin & 7;
                CP_ASYNC16(sdst + (uint32_t)(r * HPITCH + f8 * 8) * 2, gA + r * EMB + f8 * 8);
            }
            CP_COMMIT();
            CP_WAIT(1);
        } else {
            CP_WAIT(0);
        }
        __syncthreads();

        const __half* Ac = (j & 1) ? Abuf1 : Abuf0;

        // ---- mainloop: 4 k-steps of 16, warp tile 64x32 ----
        float acc[4][4][4];
        #pragma unroll
        for (int mt = 0; mt < 4; ++mt)
            #pragma unroll
            for (int nt = 0; nt < 4; ++nt)
                #pragma unroll
                for (int rr = 0; rr < 4; ++rr) acc[mt][nt][rr] = 0.0f;

        #pragma unroll
        for (int ks = 0; ks < 4; ++ks) {
            const int k0 = ks * 16;
            uint32_t a[4][4];
            #pragma unroll
            for (int mt = 0; mt < 4; ++mt) {
                const __half* ap = Ac + (mw * 64 + mt * 16 + gid) * HPITCH + k0 + 2 * tig;
                a[mt][0] = *reinterpret_cast<const uint32_t*>(ap);
                a[mt][1] = *reinterpret_cast<const uint32_t*>(ap + 8 * HPITCH);
                a[mt][2] = *reinterpret_cast<const uint32_t*>(ap + 8);
                a[mt][3] = *reinterpret_cast<const uint32_t*>(ap + 8 * HPITCH + 8);
            }
            uint32_t bb[4][2];
            #pragma unroll
            for (int nt = 0; nt < 4; ++nt) {
                const __half* bp = Bs + (nw * 32 + nt * 8 + gid) * HPITCH + k0 + 2 * tig;
                bb[nt][0] = *reinterpret_cast<const uint32_t*>(bp);
                bb[nt][1] = *reinterpret_cast<const uint32_t*>(bp + 8);
            }
            #pragma unroll
            for (int mt = 0; mt < 4; ++mt)
                #pragma unroll
                for (int nt = 0; nt < 4; ++nt)
                    mma_f16(acc[mt][nt], a[mt][0], a[mt][1], a[mt][2], a[mt][3],
                            bb[nt][0], bb[nt][1]);
        }

        __syncthreads();   // all reads of A[j] done before next prefetch overwrites

        // ---- epilogue: per-warp smem transpose -> coalesced STG.128 ----
        const int m0 = (yb + j * 8) * BM;
        #pragma unroll
        for (int mt = 0; mt < 4; ++mt) {
            #pragma unroll
            for (int nt = 0; nt < 4; ++nt) {
                const int cc = nt * 8 + 2 * tig;
                float2 v0 = make_float2(acc[mt][nt][0] + bias_r[nt][0],
                                        acc[mt][nt][1] + bias_r[nt][1]);
                float2 v1 = make_float2(acc[mt][nt][2] + bias_r[nt][0],
                                        acc[mt][nt][3] + bias_r[nt][1]);
                *reinterpret_cast<float2*>(stg + gid * 36 + cc) = v0;
                *reinterpret_cast<float2*>(stg + (gid + 8) * 36 + cc) = v1;
            }
            __syncwarp();
            const int row_base = m0 + mw * 64 + mt * 16;
            #pragma unroll
            for (int rr = 0; rr < 4; ++rr) {
                const int r = rr * 4 + sr;
                float4 v = *reinterpret_cast<const float4*>(stg + r * 36 + sc * 4);
                *reinterpret_cast<float4*>(out + (size_t)(row_base + r) * VOCAB +
                                           n0 + nw * 32 + sc * 4) = v;
            }
            __syncwarp();
        }
    }
}

// ---------------- launch ----------------
extern "C" void kernel_launch(void* const* d_in, const int* in_sizes, int n_in,
                              void* d_out, int out_size) {
    const float* emb  = (const float*)d_in[0];   // [32000, 64] f32
    const float* Wm   = (const float*)d_in[1];   // [32000, 64] f32
    const float* bias = (const float*)d_in[2];   // [32000] f32
    const int*   x    = (const int*)d_in[3];     // [4, 2048] i32
    float* out = (float*)d_out;                  // [4, 2048, 32000] f32

    wprep_kernel<<<(VOCAB * EMB / 8) / 256, 256>>>(Wm);   // 1000 blocks
    p1_kernel<<<dim3(32, BATCH), 512>>>(emb, x);
    p2_kernel<<<BATCH, 64>>>();
    p3_kernel<<<dim3(32, BATCH), 512>>>();

    cudaFuncSetAttribute(gemm_kernel, cudaFuncAttributeMaxDynamicSharedMemorySize, SMEM_SZ);
    dim3 grid(VOCAB / BN, 8);   // (250, 8)
    gemm_kernel<<<grid, 256, SMEM_SZ>>>(bias, out);
}